// round 14
// baseline (speedup 1.0000x reference)
#include <cuda_runtime.h>
#include <math.h>
#include <limits.h>

#define NRR   4096
#define NLL   16384
#define KM    8
#define TK    10
#define CF    16
#define NB    4
#define CDX   3
#define CDY   11
#define CDZ   11
#define NCELL (CDX*CDY*CDZ)      // 363
#define NCB   (NB*NCELL)         // 1452
#define WPB   8                  // warps per block
#define GRD   (NRR/WPB)          // 512 blocks, 1 radar per warp
#define KNONE 0xFFFFFFFFu
#define FULLM 0xFFFFFFFFu
#define F_LOG2PI 1.8378770664093453f

// ---------------- device scratch (zero-initialized at load) ----------------
__device__ int       g_ccnt[NCB];        // self-resetting (scan phase zeroes it)
__device__ int       g_cstart[NCB + 1];
__device__ int       g_ccur[NCB];
__device__ long long g_cent[NLL];        // ((c1<<16|c2<<8|c3) << 16) | lidar_idx
__device__ int       g_fb[NB * TK];      // lowest indices NOT in batch b
__device__ float4    g_part[NRR];
__device__ int       g_done;             // ticket; self-resetting
__device__ int       g_bar_cnt;          // barrier count; self-resetting
__device__ int       g_bar_gen;          // barrier generation; monotone across replays

__device__ __forceinline__ float softplusf(float x) {
    return log1pf(expf(-fabsf(x))) + fmaxf(x, 0.0f);
}

// grid barrier: all GRD blocks co-resident by construction (launch_bounds(256,4))
__device__ __forceinline__ void gsync() {
    __threadfence();
    __syncthreads();
    if (threadIdx.x == 0) {
        const int gen = *(volatile int*)&g_bar_gen;
        if (atomicAdd(&g_bar_cnt, 1) == GRD - 1) {
            g_bar_cnt = 0;
            __threadfence();
            *(volatile int*)&g_bar_gen = gen + 1;
        } else {
            while (*(volatile int*)&g_bar_gen == gen) {}
        }
        __threadfence();
    }
    __syncthreads();
}

// ---------------- single fused kernel ----------------
__global__ __launch_bounds__(256, 4) void k_go(
    const float* __restrict__ mu_off,  const float* __restrict__ log_sig_off,
    const float* __restrict__ mu_int,  const float* __restrict__ occ_logit,
    const float* __restrict__ mix_logit, const float* __restrict__ lfeat,
    const int* __restrict__ ridx, const int* __restrict__ lidx,
    float* __restrict__ out)
{
    __shared__ float  s_cmp[WPB][KM][9];
    __shared__ int    s_wtot[8];
    __shared__ double s_red[256][4];
    __shared__ int    s_last;

    const int tid = threadIdx.x, lane = tid & 31, wid = tid >> 5;
    const int bid = blockIdx.x;

    // ---- P0: count (32 points per block) + fb via ballot-rank (block 1) ----
    if (tid < 32) {
        const int p = bid * 32 + tid;                      // GRD*32 == NLL exactly
        const int4 v = reinterpret_cast<const int4*>(lidx)[p];
        const int cell = v.x * NCELL + (((v.y >> 4) * CDY + (v.z >> 4)) * CDZ + (v.w >> 4));
        atomicAdd(&g_ccnt[cell], 1);
    }
    if (bid == 1 && wid < NB) {                            // warp w -> batch w fillers
        const int b = wid;
        int c = 0;
        for (int j0 = 0; j0 < NLL && c < TK; j0 += 32) {
            const int j = j0 + lane;
            const bool pred = lidx[j * 4] != b;
            const unsigned m = __ballot_sync(FULLM, pred);
            if (pred) {
                const int rank = c + __popc(m & ((1u << lane) - 1u));
                if (rank < TK) g_fb[b * TK + rank] = j;
            }
            c += __popc(m);
        }
    }
    gsync();

    // ---- P1: block 0 exclusive scan over 1452 cells (shfl warp-scan) ----
    if (bid == 0) {
        const int base = tid * 6;
        int c[6], s = 0;
        #pragma unroll
        for (int q = 0; q < 6; ++q) {
            const int idx = base + q;
            c[q] = (idx < NCB) ? g_ccnt[idx] : 0;
            s += c[q];
        }
        int inc = s;                                       // warp inclusive scan
        #pragma unroll
        for (int d = 1; d < 32; d <<= 1) {
            const int vv = __shfl_up_sync(FULLM, inc, d);
            if (lane >= d) inc += vv;
        }
        if (lane == 31) s_wtot[wid] = inc;
        __syncthreads();
        if (wid == 0 && lane < 8) {                        // scan 8 warp totals
            int wv = s_wtot[lane];
            #pragma unroll
            for (int d = 1; d < 8; d <<= 1) {
                const int vv = __shfl_up_sync(0xFFu, wv, d);
                if (lane >= d) wv += vv;
            }
            s_wtot[lane] = wv - s_wtot[lane];              // exclusive
        }
        __syncthreads();
        int e = inc - s + s_wtot[wid];
        #pragma unroll
        for (int q = 0; q < 6; ++q) {
            const int idx = base + q;
            if (idx < NCB) { g_cstart[idx] = e; g_ccur[idx] = e; g_ccnt[idx] = 0; }
            e += c[q];
        }
        if (tid == 255) g_cstart[NCB] = e;
    }
    gsync();

    // ---- P2: scatter ----
    if (tid < 32) {
        const int p = bid * 32 + tid;
        const int4 v = reinterpret_cast<const int4*>(lidx)[p];
        const int cell = v.x * NCELL + (((v.y >> 4) * CDY + (v.z >> 4)) * CDZ + (v.w >> 4));
        const int pos = atomicAdd(&g_ccur[cell], 1);
        g_cent[pos] = (((long long)((v.y << 16) | (v.z << 8) | v.w)) << 16) | (long long)p;
    }
    gsync();

    // ---- P3: per-radar search (persistent per-lane top-10, shell escalation) ----
    {
        const int i = bid * WPB + wid;
        const int4 r = reinterpret_cast<const int4*>(ridx)[i];
        const int b = r.x, r1 = r.y, r2 = r.z, r3 = r.w;
        const int cx = r1 >> 4, cy = r2 >> 4, cz = r3 >> 4;
        const int cbase = b * NCELL;
        const int bbeg = g_cstart[cbase];
        const int bend = g_cstart[cbase + NCELL];
        const int nbL  = bend - bbeg;

        unsigned lst[TK];
        #pragma unroll
        for (int s = 0; s < TK; ++s) lst[s] = KNONE;

        // scans [beg,end) raw entries, inserting every point (gated by current 10th)
        auto scan_span = [&](int beg, int end) {
            for (int j = beg + lane; j < end; j += 32) {
                const long long e = g_cent[j];
                const int p  = (int)(e >> 16);
                const int d3 = (p & 255) - r3;
                const int d2 = ((p >> 8) & 255) - r2;
                const int d1 = ((p >> 16) & 255) - r1;
                const unsigned dd = (unsigned)(d1 * d1 + d2 * d2 + d3 * d3);
                unsigned key = (dd << 16) | ((unsigned)e & 0xFFFFu);
                if (key < lst[TK - 1]) {
                    #pragma unroll
                    for (int s = 0; s < TK; ++s) {         // sorted bubble-insert
                        const unsigned lo = min(key, lst[s]);
                        key = max(key, lst[s]);
                        lst[s] = lo;
                    }
                }
            }
        };

        int px0 = 1, px1 = 0, py0 = 1, py1 = 0, pz0 = 1, pz1 = 0;   // empty prev
        bool first = true;
        #pragma unroll 1
        for (int R = 1;; ++R) {
            const int x0 = max(cx - R, 0), x1 = min(cx + R, CDX - 1);
            const int y0 = max(cy - R, 0), y1 = min(cy + R, CDY - 1);
            const int z0 = max(cz - R, 0), z1 = min(cz + R, CDZ - 1);
            int g = INT_MAX;
            if (x0 > 0)       g = min(g, r1 - x0 * 16);
            if (x1 < CDX - 1) g = min(g, (x1 + 1) * 16 - r1);
            if (y0 > 0)       g = min(g, r2 - y0 * 16);
            if (y1 < CDY - 1) g = min(g, (y1 + 1) * 16 - r2);
            if (z0 > 0)       g = min(g, r3 - z0 * 16);
            if (z1 < CDZ - 1) g = min(g, (z1 + 1) * 16 - r3);
            const bool whole = (g == INT_MAX);
            const unsigned g2c = whole ? 65535u
                                       : (unsigned)min((long long)g * g, 65535LL);

            if (first) {
                // parallel bound prefetch: at R=1 nrows <= 9
                const int ny = y1 - y0 + 1;
                const int nrows = (x1 - x0 + 1) * ny;
                int begL = 0, endL = 0;
                if (lane < nrows) {
                    const int xx = x0 + lane / ny;
                    const int yy = y0 + lane % ny;
                    const int crow = cbase + (xx * CDY + yy) * CDZ;
                    begL = g_cstart[crow + z0];
                    endL = g_cstart[crow + z1 + 1];
                }
                for (int s = 0; s < nrows; ++s)
                    scan_span(__shfl_sync(FULLM, begL, s), __shfl_sync(FULLM, endL, s));
                first = false;
            } else {
                // shell-only: scan cells not covered by prev region
                #pragma unroll 1
                for (int xx = x0; xx <= x1; ++xx) {
                    #pragma unroll 1
                    for (int yy = y0; yy <= y1; ++yy) {
                        const int crow = cbase + (xx * CDY + yy) * CDZ;
                        if (xx >= px0 && xx <= px1 && yy >= py0 && yy <= py1) {
                            scan_span(g_cstart[crow + z0], g_cstart[crow + pz0]);
                            scan_span(g_cstart[crow + pz1 + 1], g_cstart[crow + z1 + 1]);
                        } else {
                            scan_span(g_cstart[crow + z0], g_cstart[crow + z1 + 1]);
                        }
                    }
                }
            }
            px0 = x0; px1 = x1; py0 = y0; py1 = y1; pz0 = z0; pz1 = z1;

            // stop check: >=TK points strictly inside guard radius (register-only)
            const unsigned thr = g2c << 16;
            int cq = 0;
            #pragma unroll
            for (int s = 0; s < TK; ++s) cq += (lst[s] < thr);
            const unsigned cnt = __reduce_add_sync(FULLM, (unsigned)cq);
            if (cnt >= TK || whole) break;
        }

        // merge: 10 rounds of warp-min over sorted lane heads (keys unique)
        unsigned mykey = KNONE;
        #pragma unroll
        for (int t = 0; t < TK; ++t) {
            const unsigned m = __reduce_min_sync(FULLM, lst[0]);
            if (lane == t) mykey = m;
            if (lst[0] == m) {
                #pragma unroll
                for (int s = 0; s < TK - 1; ++s) lst[s] = lst[s + 1];
                lst[TK - 1] = KNONE;
            }
        }

        // per-component precompute (lanes 0..7, width-8 trees)
        const int k = lane;
        float v = (k < KM) ? mix_logit[i * KM + k] : -INFINITY;
        float mx = v;
        #pragma unroll
        for (int d = 4; d; d >>= 1) mx = fmaxf(mx, __shfl_xor_sync(FULLM, mx, d));
        const float ex = (k < KM) ? expf(v - mx) : 0.0f;
        float sm = ex;
        #pragma unroll
        for (int d = 4; d; d >>= 1) sm += __shfl_xor_sync(FULLM, sm, d);
        const float lz = mx + logf(sm);

        float o = (k < KM) ? occ_logit[i * KM + k] : -INFINITY;
        #pragma unroll
        for (int d = 4; d; d >>= 1) o = fmaxf(o, __shfl_xor_sync(FULLM, o, d));

        if (k < KM) {
            const int bk = (i * KM + k) * 3;
            const float l0 = log_sig_off[bk], l1 = log_sig_off[bk + 1], l2 = log_sig_off[bk + 2];
            s_cmp[wid][k][0] = v - lz;
            s_cmp[wid][k][1] = mu_off[bk];
            s_cmp[wid][k][2] = mu_off[bk + 1];
            s_cmp[wid][k][3] = mu_off[bk + 2];
            s_cmp[wid][k][4] = 1.0f / (expf(2.0f * l0) + 1e-12f);
            s_cmp[wid][k][5] = 1.0f / (expf(2.0f * l1) + 1e-12f);
            s_cmp[wid][k][6] = 1.0f / (expf(2.0f * l2) + 1e-12f);
            s_cmp[wid][k][7] = 2.0f * (l0 + l1 + l2) + 3.0f * F_LOG2PI;
            s_cmp[wid][k][8] = mu_int[i * KM + k];
        }
        __syncwarp();

        // per-slot MDN + intensity (lanes 0..9)
        const bool matched = nbL > 0;
        const unsigned rm = __ballot_sync(FULLM, mykey != KNONE && lane < TK);
        const int nvalid = __popc(rm);
        float SL = 0.0f, SI = 0.0f;
        if (lane < TK) {
            const int j = (mykey != KNONE) ? (int)(mykey & 0xFFFFu)
                                           : g_fb[b * TK + (lane - nvalid)];
            const int4 lv = reinterpret_cast<const int4*>(lidx)[j];
            const float y0 = matched ? (float)(lv.w - r3) : 0.0f;
            const float y1 = matched ? (float)(lv.z - r2) : 0.0f;
            const float y2 = matched ? (float)(lv.y - r1) : 0.0f;
            const float* f = lfeat + j * CF;
            const float gi = matched ? 0.25f * (f[3] + f[7] + f[11] + f[15]) : 0.0f;

            float lp[KM]; float pm = -INFINITY;
            #pragma unroll
            for (int kk = 0; kk < KM; ++kk) {
                const float d0 = y0 - s_cmp[wid][kk][1];
                const float d1 = y1 - s_cmp[wid][kk][2];
                const float d2 = y2 - s_cmp[wid][kk][3];
                const float qv = d0 * d0 * s_cmp[wid][kk][4] + d1 * d1 * s_cmp[wid][kk][5]
                               + d2 * d2 * s_cmp[wid][kk][6];
                lp[kk] = -0.5f * (qv + s_cmp[wid][kk][7]) + s_cmp[wid][kk][0];
                pm = fmaxf(pm, lp[kk]);
            }
            float se = 0.0f;
            #pragma unroll
            for (int kk = 0; kk < KM; ++kk) se += expf(lp[kk] - pm);
            const float logp = pm + logf(se);
            SL = logp;
            float ai = 0.0f;
            #pragma unroll
            for (int kk = 0; kk < KM; ++kk)
                ai += expf(lp[kk] - logp) * fabsf(s_cmp[wid][kk][8] - gi);
            SI = ai;
        }
        #pragma unroll
        for (int d = 16; d; d >>= 1) {
            SL += __shfl_xor_sync(FULLM, SL, d);
            SI += __shfl_xor_sync(FULLM, SI, d);
        }
        if (lane == 0) {
            const float tgt = matched ? 1.0f : 0.0f;
            const float occ = tgt * softplusf(-o) + (1.0f - tgt) * softplusf(o);
            g_part[i] = make_float4(occ, tgt, tgt * SL, tgt * SI);
        }
    }

    // ---- P4: last-finishing-block deterministic reduction (ticket) ----
    __threadfence();
    __syncthreads();
    if (tid == 0) s_last = (atomicAdd(&g_done, 1) == GRD - 1);
    __syncthreads();
    if (s_last) {
        __threadfence();
        double a0 = 0, a1 = 0, a2 = 0, a3 = 0;
        for (int q = tid; q < NRR; q += 256) {
            const float4 p = g_part[q];
            a0 += p.x; a1 += p.y; a2 += p.z; a3 += p.w;
        }
        s_red[tid][0] = a0; s_red[tid][1] = a1; s_red[tid][2] = a2; s_red[tid][3] = a3;
        __syncthreads();
        for (int s = 128; s; s >>= 1) {
            if (tid < s) {
                s_red[tid][0] += s_red[tid + s][0];
                s_red[tid][1] += s_red[tid + s][1];
                s_red[tid][2] += s_red[tid + s][2];
                s_red[tid][3] += s_red[tid + s][3];
            }
            __syncthreads();
        }
        if (tid == 0) {
            const double occ_loss = s_red[0][0] / (double)NRR;
            const double cntm     = s_red[0][1];
            const double mdn_nll  = -s_red[0][2] / (cntm * (double)TK);
            const double int_loss =  s_red[0][3] / (cntm * (double)TK * (double)KM);
            out[0] = (float)(0.2 * occ_loss + 1.0 * mdn_nll + 0.1 * int_loss);
            g_done = 0;   // reset for next replay
        }
    }
}

// ---------------- launch ----------------
extern "C" void kernel_launch(void* const* d_in, const int* in_sizes, int n_in,
                              void* d_out, int out_size) {
    const float* mu_off      = (const float*)d_in[0];
    const float* log_sig_off = (const float*)d_in[1];
    const float* mu_int      = (const float*)d_in[2];
    const float* occ_logit   = (const float*)d_in[3];
    const float* mix_logit   = (const float*)d_in[4];
    const float* lfeat       = (const float*)d_in[5];
    const int*   ridx        = (const int*)d_in[6];
    const int*   lidx        = (const int*)d_in[7];
    (void)in_sizes; (void)n_in; (void)out_size;

    k_go<<<GRD, 256>>>(mu_off, log_sig_off, mu_int, occ_logit, mix_logit,
                       lfeat, ridx, lidx, (float*)d_out);
}

// round 15
// speedup vs baseline: 1.4128x; 1.4128x over previous
#include <cuda_runtime.h>
#include <math.h>
#include <limits.h>

#define NRR   4096
#define NLL   16384
#define KM    8
#define TK    10
#define CF    16
#define NB    4
#define CDX   3
#define CDY   11
#define CDZ   11
#define NCELL (CDX*CDY*CDZ)      // 363
#define NCB   (NB*NCELL)         // 1452
#define WPB   8                  // warps per block
#define GRD   (NRR/WPB)          // 512 blocks, 1 radar per warp
#define NGRP  32                 // barrier groups
#define GSZ   (GRD/NGRP)         // 16 blocks per group
#define KNONE 0xFFFFFFFFu
#define FULLM 0xFFFFFFFFu
#define F_LOG2PI 1.8378770664093453f

// ---------------- device scratch (zero-initialized at load) ----------------
struct __align__(128) PadCnt { int v; int pad[31]; };

__device__ int       g_ccnt[NCB];        // self-resetting (scan phase zeroes it)
__device__ int       g_cstart[NCB + 1];
__device__ int       g_ccur[NCB];
__device__ long long g_cent[NLL];        // ((c1<<16|c2<<8|c3) << 16) | lidar_idx
__device__ int       g_fb[NB * TK];      // lowest indices NOT in batch b
__device__ float4    g_part[NRR];
__device__ PadCnt    g_grp[NGRP];        // per-group arrival counters (self-reset)
__device__ PadCnt    g_root;             // root counter (self-reset)
__device__ PadCnt    g_dgrp[NGRP];       // exit-ticket group counters (self-reset)
__device__ PadCnt    g_droot;            // exit-ticket root (self-reset)
__device__ int       g_bar_gen;          // generation; monotone across replays

__device__ __forceinline__ float softplusf(float x) {
    return log1pf(expf(-fabsf(x))) + fmaxf(x, 0.0f);
}

// hierarchical grid barrier: all GRD blocks co-resident (launch_bounds(256,4))
__device__ __forceinline__ void gsync(int bid) {
    __threadfence();
    __syncthreads();
    if (threadIdx.x == 0) {
        const int gen = *(volatile int*)&g_bar_gen;
        const int grp = bid >> 4;                       // bid / GSZ
        if (atomicAdd(&g_grp[grp].v, 1) == GSZ - 1) {
            g_grp[grp].v = 0;                           // reset before root arrive
            if (atomicAdd(&g_root.v, 1) == NGRP - 1) {
                g_root.v = 0;
                __threadfence();
                *(volatile int*)&g_bar_gen = gen + 1;
            }
        }
        while (*(volatile int*)&g_bar_gen == gen) __nanosleep(64);
        __threadfence();
    }
    __syncthreads();
}

// ---------------- single fused kernel ----------------
__global__ __launch_bounds__(256, 4) void k_go(
    const float* __restrict__ mu_off,  const float* __restrict__ log_sig_off,
    const float* __restrict__ mu_int,  const float* __restrict__ occ_logit,
    const float* __restrict__ mix_logit, const float* __restrict__ lfeat,
    const int* __restrict__ ridx, const int* __restrict__ lidx,
    float* __restrict__ out)
{
    __shared__ float  s_cmp[WPB][KM][9];
    __shared__ int    s_wtot[8];
    __shared__ double s_red[256][4];
    __shared__ int    s_last;

    const int tid = threadIdx.x, lane = tid & 31, wid = tid >> 5;
    const int bid = blockIdx.x;

    // ---- P0: count (32 points per block) + fb via ballot-rank (block 1) ----
    if (tid < 32) {
        const int p = bid * 32 + tid;                      // GRD*32 == NLL exactly
        const int4 v = reinterpret_cast<const int4*>(lidx)[p];
        const int cell = v.x * NCELL + (((v.y >> 4) * CDY + (v.z >> 4)) * CDZ + (v.w >> 4));
        atomicAdd(&g_ccnt[cell], 1);
    }
    if (bid == 1 && wid < NB) {                            // warp w -> batch w fillers
        const int b = wid;
        int c = 0;
        for (int j0 = 0; j0 < NLL && c < TK; j0 += 32) {
            const int j = j0 + lane;
            const bool pred = lidx[j * 4] != b;
            const unsigned m = __ballot_sync(FULLM, pred);
            if (pred) {
                const int rank = c + __popc(m & ((1u << lane) - 1u));
                if (rank < TK) g_fb[b * TK + rank] = j;
            }
            c += __popc(m);
        }
    }
    gsync(bid);

    // ---- P1: block 0 exclusive scan over 1452 cells (shfl warp-scan) ----
    if (bid == 0) {
        const int base = tid * 6;
        int c[6], s = 0;
        #pragma unroll
        for (int q = 0; q < 6; ++q) {
            const int idx = base + q;
            c[q] = (idx < NCB) ? g_ccnt[idx] : 0;
            s += c[q];
        }
        int inc = s;                                       // warp inclusive scan
        #pragma unroll
        for (int d = 1; d < 32; d <<= 1) {
            const int vv = __shfl_up_sync(FULLM, inc, d);
            if (lane >= d) inc += vv;
        }
        if (lane == 31) s_wtot[wid] = inc;
        __syncthreads();
        if (wid == 0 && lane < 8) {                        // scan 8 warp totals
            int wv = s_wtot[lane];
            #pragma unroll
            for (int d = 1; d < 8; d <<= 1) {
                const int vv = __shfl_up_sync(0xFFu, wv, d);
                if (lane >= d) wv += vv;
            }
            s_wtot[lane] = wv - s_wtot[lane];              // exclusive
        }
        __syncthreads();
        int e = inc - s + s_wtot[wid];
        #pragma unroll
        for (int q = 0; q < 6; ++q) {
            const int idx = base + q;
            if (idx < NCB) { g_cstart[idx] = e; g_ccur[idx] = e; g_ccnt[idx] = 0; }
            e += c[q];
        }
        if (tid == 255) g_cstart[NCB] = e;
    }
    gsync(bid);

    // ---- P2: scatter ----
    if (tid < 32) {
        const int p = bid * 32 + tid;
        const int4 v = reinterpret_cast<const int4*>(lidx)[p];
        const int cell = v.x * NCELL + (((v.y >> 4) * CDY + (v.z >> 4)) * CDZ + (v.w >> 4));
        const int pos = atomicAdd(&g_ccur[cell], 1);
        g_cent[pos] = (((long long)((v.y << 16) | (v.z << 8) | v.w)) << 16) | (long long)p;
    }
    gsync(bid);

    // ---- P3: per-radar search (per-lane register top-10, filtered insert) ----
    {
        const int i = bid * WPB + wid;
        const int4 r = reinterpret_cast<const int4*>(ridx)[i];
        const int b = r.x, r1 = r.y, r2 = r.z, r3 = r.w;
        const int cx = r1 >> 4, cy = r2 >> 4, cz = r3 >> 4;
        const int cbase = b * NCELL;
        const int bbeg = g_cstart[cbase];
        const int bend = g_cstart[cbase + NCELL];
        const int nbL  = bend - bbeg;

        unsigned lst[TK];
        #pragma unroll 1
        for (int R = 1;; ++R) {
            const int x0 = max(cx - R, 0), x1 = min(cx + R, CDX - 1);
            const int y0 = max(cy - R, 0), y1 = min(cy + R, CDY - 1);
            const int z0 = max(cz - R, 0), z1 = min(cz + R, CDZ - 1);
            int g = INT_MAX;
            if (x0 > 0)       g = min(g, r1 - x0 * 16);
            if (x1 < CDX - 1) g = min(g, (x1 + 1) * 16 - r1);
            if (y0 > 0)       g = min(g, r2 - y0 * 16);
            if (y1 < CDY - 1) g = min(g, (y1 + 1) * 16 - r2);
            if (z0 > 0)       g = min(g, r3 - z0 * 16);
            if (z1 < CDZ - 1) g = min(g, (z1 + 1) * 16 - r3);
            const bool whole = (g == INT_MAX);
            const unsigned g2 = whole ? 0x7FFFFFFFu : (unsigned)(g * g);

            #pragma unroll
            for (int s = 0; s < TK; ++s) lst[s] = KNONE;
            int cntL = 0;

            #pragma unroll 1
            for (int xx = x0; xx <= x1; ++xx) {
                #pragma unroll 1
                for (int yy = y0; yy <= y1; ++yy) {
                    const int crow = cbase + (xx * CDY + yy) * CDZ;
                    const int beg = g_cstart[crow + z0];
                    const int end = g_cstart[crow + z1 + 1];
                    for (int j = beg + lane; j < end; j += 32) {
                        const long long e = g_cent[j];
                        const int p  = (int)(e >> 16);
                        const int d3 = (p & 255) - r3;
                        const int d2 = ((p >> 8) & 255) - r2;
                        const int d1 = ((p >> 16) & 255) - r1;
                        const unsigned dd = (unsigned)(d1 * d1 + d2 * d2 + d3 * d3);
                        if (dd < g2) {
                            ++cntL;
                            unsigned key = (dd << 16) | ((unsigned)e & 0xFFFFu);
                            #pragma unroll
                            for (int s = 0; s < TK; ++s) {   // sorted bubble-insert
                                const unsigned lo = min(key, lst[s]);
                                key = max(key, lst[s]);
                                lst[s] = lo;
                            }
                        }
                    }
                }
            }
            const unsigned cnt = __reduce_add_sync(FULLM, (unsigned)cntL);
            if (cnt >= TK || whole) break;
        }

        // merge: 10 rounds of warp-min over sorted lane heads (keys unique)
        unsigned mykey = KNONE;
        #pragma unroll
        for (int t = 0; t < TK; ++t) {
            const unsigned m = __reduce_min_sync(FULLM, lst[0]);
            if (lane == t) mykey = m;
            if (lst[0] == m) {
                #pragma unroll
                for (int s = 0; s < TK - 1; ++s) lst[s] = lst[s + 1];
                lst[TK - 1] = KNONE;
            }
        }

        // per-component precompute (lanes 0..7, width-8 trees)
        const int k = lane;
        float v = (k < KM) ? mix_logit[i * KM + k] : -INFINITY;
        float mx = v;
        #pragma unroll
        for (int d = 4; d; d >>= 1) mx = fmaxf(mx, __shfl_xor_sync(FULLM, mx, d));
        const float ex = (k < KM) ? expf(v - mx) : 0.0f;
        float sm = ex;
        #pragma unroll
        for (int d = 4; d; d >>= 1) sm += __shfl_xor_sync(FULLM, sm, d);
        const float lz = mx + logf(sm);

        float o = (k < KM) ? occ_logit[i * KM + k] : -INFINITY;
        #pragma unroll
        for (int d = 4; d; d >>= 1) o = fmaxf(o, __shfl_xor_sync(FULLM, o, d));

        if (k < KM) {
            const int bk = (i * KM + k) * 3;
            const float l0 = log_sig_off[bk], l1 = log_sig_off[bk + 1], l2 = log_sig_off[bk + 2];
            s_cmp[wid][k][0] = v - lz;
            s_cmp[wid][k][1] = mu_off[bk];
            s_cmp[wid][k][2] = mu_off[bk + 1];
            s_cmp[wid][k][3] = mu_off[bk + 2];
            s_cmp[wid][k][4] = 1.0f / (expf(2.0f * l0) + 1e-12f);
            s_cmp[wid][k][5] = 1.0f / (expf(2.0f * l1) + 1e-12f);
            s_cmp[wid][k][6] = 1.0f / (expf(2.0f * l2) + 1e-12f);
            s_cmp[wid][k][7] = 2.0f * (l0 + l1 + l2) + 3.0f * F_LOG2PI;
            s_cmp[wid][k][8] = mu_int[i * KM + k];
        }
        __syncwarp();

        // per-slot MDN + intensity (lanes 0..9)
        const bool matched = nbL > 0;
        const unsigned rm = __ballot_sync(FULLM, mykey != KNONE && lane < TK);
        const int nvalid = __popc(rm);
        float SL = 0.0f, SI = 0.0f;
        if (lane < TK) {
            const int j = (mykey != KNONE) ? (int)(mykey & 0xFFFFu)
                                           : g_fb[b * TK + (lane - nvalid)];
            const int4 lv = reinterpret_cast<const int4*>(lidx)[j];
            const float y0 = matched ? (float)(lv.w - r3) : 0.0f;
            const float y1 = matched ? (float)(lv.z - r2) : 0.0f;
            const float y2 = matched ? (float)(lv.y - r1) : 0.0f;
            const float* f = lfeat + j * CF;
            const float gi = matched ? 0.25f * (f[3] + f[7] + f[11] + f[15]) : 0.0f;

            float lp[KM]; float pm = -INFINITY;
            #pragma unroll
            for (int kk = 0; kk < KM; ++kk) {
                const float d0 = y0 - s_cmp[wid][kk][1];
                const float d1 = y1 - s_cmp[wid][kk][2];
                const float d2 = y2 - s_cmp[wid][kk][3];
                const float qv = d0 * d0 * s_cmp[wid][kk][4] + d1 * d1 * s_cmp[wid][kk][5]
                               + d2 * d2 * s_cmp[wid][kk][6];
                lp[kk] = -0.5f * (qv + s_cmp[wid][kk][7]) + s_cmp[wid][kk][0];
                pm = fmaxf(pm, lp[kk]);
            }
            float se = 0.0f;
            #pragma unroll
            for (int kk = 0; kk < KM; ++kk) se += expf(lp[kk] - pm);
            const float logp = pm + logf(se);
            SL = logp;
            float ai = 0.0f;
            #pragma unroll
            for (int kk = 0; kk < KM; ++kk)
                ai += expf(lp[kk] - logp) * fabsf(s_cmp[wid][kk][8] - gi);
            SI = ai;
        }
        #pragma unroll
        for (int d = 16; d; d >>= 1) {
            SL += __shfl_xor_sync(FULLM, SL, d);
            SI += __shfl_xor_sync(FULLM, SI, d);
        }
        if (lane == 0) {
            const float tgt = matched ? 1.0f : 0.0f;
            const float occ = tgt * softplusf(-o) + (1.0f - tgt) * softplusf(o);
            g_part[i] = make_float4(occ, tgt, tgt * SL, tgt * SI);
        }
    }

    // ---- P4: hierarchical exit ticket; last block reduces deterministically ----
    __threadfence();
    __syncthreads();
    if (tid == 0) {
        int lastf = 0;
        const int grp = bid >> 4;
        if (atomicAdd(&g_dgrp[grp].v, 1) == GSZ - 1) {
            g_dgrp[grp].v = 0;
            if (atomicAdd(&g_droot.v, 1) == NGRP - 1) {
                g_droot.v = 0;
                lastf = 1;
            }
        }
        s_last = lastf;
    }
    __syncthreads();
    if (s_last) {
        __threadfence();
        double a0 = 0, a1 = 0, a2 = 0, a3 = 0;
        for (int q = tid; q < NRR; q += 256) {
            const float4 p = g_part[q];
            a0 += p.x; a1 += p.y; a2 += p.z; a3 += p.w;
        }
        s_red[tid][0] = a0; s_red[tid][1] = a1; s_red[tid][2] = a2; s_red[tid][3] = a3;
        __syncthreads();
        for (int s = 128; s; s >>= 1) {
            if (tid < s) {
                s_red[tid][0] += s_red[tid + s][0];
                s_red[tid][1] += s_red[tid + s][1];
                s_red[tid][2] += s_red[tid + s][2];
                s_red[tid][3] += s_red[tid + s][3];
            }
            __syncthreads();
        }
        if (tid == 0) {
            const double occ_loss = s_red[0][0] / (double)NRR;
            const double cntm     = s_red[0][1];
            const double mdn_nll  = -s_red[0][2] / (cntm * (double)TK);
            const double int_loss =  s_red[0][3] / (cntm * (double)TK * (double)KM);
            out[0] = (float)(0.2 * occ_loss + 1.0 * mdn_nll + 0.1 * int_loss);
        }
    }
}

// ---------------- launch ----------------
extern "C" void kernel_launch(void* const* d_in, const int* in_sizes, int n_in,
                              void* d_out, int out_size) {
    const float* mu_off      = (const float*)d_in[0];
    const float* log_sig_off = (const float*)d_in[1];
    const float* mu_int      = (const float*)d_in[2];
    const float* occ_logit   = (const float*)d_in[3];
    const float* mix_logit   = (const float*)d_in[4];
    const float* lfeat       = (const float*)d_in[5];
    const int*   ridx        = (const int*)d_in[6];
    const int*   lidx        = (const int*)d_in[7];
    (void)in_sizes; (void)n_in; (void)out_size;

    k_go<<<GRD, 256>>>(mu_off, log_sig_off, mu_int, occ_logit, mix_logit,
                       lfeat, ridx, lidx, (float*)d_out);
}

// round 17
// speedup vs baseline: 1.4690x; 1.0398x over previous
#include <cuda_runtime.h>
#include <math.h>
#include <limits.h>

#define NRR   4096
#define NLL   16384
#define KM    8
#define TK    10
#define CF    16
#define NB    4
#define CDX   3
#define CDY   11
#define CDZ   11
#define NCELL (CDX*CDY*CDZ)      // 363
#define NCB   (NB*NCELL)         // 1452
#define WPB   8                  // warps per block
#define GRD   (NRR/WPB)          // 512 blocks, 1 radar per warp
#define KNONE 0xFFFFFFFFu
#define FULLM 0xFFFFFFFFu
#define F_LOG2PI 1.8378770664093453f

// ---------------- device scratch (zero-initialized at load) ----------------
__device__ int       g_ccnt[NCB];        // lidar cell counts (self-resetting)
__device__ int       g_cstart[NCB + 1];
__device__ int       g_ccur[NCB];
__device__ int       g_rcnt[NCB];        // radar cell counts (self-resetting)
__device__ int       g_rcur[NCB];
__device__ int       g_rord[NRR];        // radar ids sorted by (batch, cell)
__device__ long long g_cent[NLL];        // ((c1<<16|c2<<8|c3) << 16) | lidar_idx
__device__ int       g_fb[NB * TK];      // lowest indices NOT in batch b
__device__ float4    g_part[NRR];
__device__ int       g_done;             // ticket; self-resetting
__device__ int       g_bar_cnt;          // barrier count; self-resetting
__device__ int       g_bar_gen;          // generation; monotone across replays

__device__ __forceinline__ float softplusf(float x) {
    return log1pf(expf(-fabsf(x))) + fmaxf(x, 0.0f);
}

// grid barrier: all GRD blocks co-resident by construction (launch_bounds(256,4))
__device__ __forceinline__ void gsync() {
    __threadfence();
    __syncthreads();
    if (threadIdx.x == 0) {
        const int gen = *(volatile int*)&g_bar_gen;
        if (atomicAdd(&g_bar_cnt, 1) == GRD - 1) {
            g_bar_cnt = 0;
            __threadfence();
            *(volatile int*)&g_bar_gen = gen + 1;
        } else {
            while (*(volatile int*)&g_bar_gen == gen) {}
        }
        __threadfence();
    }
    __syncthreads();
}

// ---------------- single fused kernel ----------------
__global__ __launch_bounds__(256, 4) void k_go(
    const float* __restrict__ mu_off,  const float* __restrict__ log_sig_off,
    const float* __restrict__ mu_int,  const float* __restrict__ occ_logit,
    const float* __restrict__ mix_logit, const float* __restrict__ lfeat,
    const int* __restrict__ ridx, const int* __restrict__ lidx,
    float* __restrict__ out)
{
    __shared__ float  s_cmp[WPB][KM][9];
    __shared__ int    s_wtot[8];
    __shared__ double s_red[256][4];
    __shared__ int    s_last;

    const int tid = threadIdx.x, lane = tid & 31, wid = tid >> 5;
    const int bid = blockIdx.x;

    // ---- P0: lidar count (32/block) + radar count (8/block) + fb (block 2) ----
    if (tid < 32) {
        const int p = bid * 32 + tid;                      // GRD*32 == NLL exactly
        const int4 v = reinterpret_cast<const int4*>(lidx)[p];
        const int cell = v.x * NCELL + (((v.y >> 4) * CDY + (v.z >> 4)) * CDZ + (v.w >> 4));
        atomicAdd(&g_ccnt[cell], 1);
    } else if (tid >= 64 && tid < 64 + WPB) {
        const int p = bid * WPB + (tid - 64);              // GRD*8 == NRR exactly
        const int4 v = reinterpret_cast<const int4*>(ridx)[p];
        const int cell = v.x * NCELL + (((v.y >> 4) * CDY + (v.z >> 4)) * CDZ + (v.w >> 4));
        atomicAdd(&g_rcnt[cell], 1);
    }
    if (bid == 2 && wid < NB) {                            // warp w -> batch w fillers
        const int b = wid;
        int c = 0;
        for (int j0 = 0; j0 < NLL && c < TK; j0 += 32) {
            const int j = j0 + lane;
            const bool pred = lidx[j * 4] != b;
            const unsigned m = __ballot_sync(FULLM, pred);
            if (pred) {
                const int rank = c + __popc(m & ((1u << lane) - 1u));
                if (rank < TK) g_fb[b * TK + rank] = j;
            }
            c += __popc(m);
        }
    }
    gsync();

    // ---- P1: block 0 scans lidar cells; block 1 scans radar cells (parallel) ----
    if (bid < 2) {
        int* __restrict__ cnt = (bid == 0) ? g_ccnt : g_rcnt;
        const int base = tid * 6;
        int c[6], s = 0;
        #pragma unroll
        for (int q = 0; q < 6; ++q) {
            const int idx = base + q;
            c[q] = (idx < NCB) ? cnt[idx] : 0;
            s += c[q];
        }
        int inc = s;                                       // warp inclusive scan
        #pragma unroll
        for (int d = 1; d < 32; d <<= 1) {
            const int vv = __shfl_up_sync(FULLM, inc, d);
            if (lane >= d) inc += vv;
        }
        if (lane == 31) s_wtot[wid] = inc;
        __syncthreads();
        if (wid == 0 && lane < 8) {                        // scan 8 warp totals
            int wv = s_wtot[lane];
            #pragma unroll
            for (int d = 1; d < 8; d <<= 1) {
                const int vv = __shfl_up_sync(0xFFu, wv, d);
                if (lane >= d) wv += vv;
            }
            s_wtot[lane] = wv - s_wtot[lane];              // exclusive
        }
        __syncthreads();
        int e = inc - s + s_wtot[wid];
        if (bid == 0) {
            #pragma unroll
            for (int q = 0; q < 6; ++q) {
                const int idx = base + q;
                if (idx < NCB) { g_cstart[idx] = e; g_ccur[idx] = e; g_ccnt[idx] = 0; }
                e += c[q];
            }
            if (tid == 255) g_cstart[NCB] = e;
        } else {
            #pragma unroll
            for (int q = 0; q < 6; ++q) {
                const int idx = base + q;
                if (idx < NCB) { g_rcur[idx] = e; g_rcnt[idx] = 0; }
                e += c[q];
            }
        }
    }
    gsync();

    // ---- P2: scatter lidars + scatter radars ----
    if (tid < 32) {
        const int p = bid * 32 + tid;
        const int4 v = reinterpret_cast<const int4*>(lidx)[p];
        const int cell = v.x * NCELL + (((v.y >> 4) * CDY + (v.z >> 4)) * CDZ + (v.w >> 4));
        const int pos = atomicAdd(&g_ccur[cell], 1);
        g_cent[pos] = (((long long)((v.y << 16) | (v.z << 8) | v.w)) << 16) | (long long)p;
    } else if (tid >= 64 && tid < 64 + WPB) {
        const int p = bid * WPB + (tid - 64);
        const int4 v = reinterpret_cast<const int4*>(ridx)[p];
        const int cell = v.x * NCELL + (((v.y >> 4) * CDY + (v.z >> 4)) * CDZ + (v.w >> 4));
        const int pos = atomicAdd(&g_rcur[cell], 1);
        g_rord[pos] = p;
    }
    gsync();

    // ---- P3: per-radar search; warps in a block share one neighborhood (L1) ----
    {
        const int i = g_rord[bid * WPB + wid];             // cell-sorted radar id
        const int4 r = reinterpret_cast<const int4*>(ridx)[i];
        const int b = r.x, r1 = r.y, r2 = r.z, r3 = r.w;
        const int cx = r1 >> 4, cy = r2 >> 4, cz = r3 >> 4;
        const int cbase = b * NCELL;
        const int bbeg = g_cstart[cbase];
        const int bend = g_cstart[cbase + NCELL];
        const int nbL  = bend - bbeg;

        unsigned lst[TK];
        #pragma unroll 1
        for (int R = 1;; ++R) {
            const int x0 = max(cx - R, 0), x1 = min(cx + R, CDX - 1);
            const int y0 = max(cy - R, 0), y1 = min(cy + R, CDY - 1);
            const int z0 = max(cz - R, 0), z1 = min(cz + R, CDZ - 1);
            int g = INT_MAX;
            if (x0 > 0)       g = min(g, r1 - x0 * 16);
            if (x1 < CDX - 1) g = min(g, (x1 + 1) * 16 - r1);
            if (y0 > 0)       g = min(g, r2 - y0 * 16);
            if (y1 < CDY - 1) g = min(g, (y1 + 1) * 16 - r2);
            if (z0 > 0)       g = min(g, r3 - z0 * 16);
            if (z1 < CDZ - 1) g = min(g, (z1 + 1) * 16 - r3);
            const bool whole = (g == INT_MAX);
            const unsigned g2 = whole ? 0x7FFFFFFFu : (unsigned)(g * g);

            #pragma unroll
            for (int s = 0; s < TK; ++s) lst[s] = KNONE;
            int cntL = 0;

            #pragma unroll 1
            for (int xx = x0; xx <= x1; ++xx) {
                #pragma unroll 1
                for (int yy = y0; yy <= y1; ++yy) {
                    const int crow = cbase + (xx * CDY + yy) * CDZ;
                    const int beg = g_cstart[crow + z0];
                    const int end = g_cstart[crow + z1 + 1];
                    for (int j = beg + lane; j < end; j += 32) {
                        const long long e = g_cent[j];
                        const int p  = (int)(e >> 16);
                        const int d3 = (p & 255) - r3;
                        const int d2 = ((p >> 8) & 255) - r2;
                        const int d1 = ((p >> 16) & 255) - r1;
                        const unsigned dd = (unsigned)(d1 * d1 + d2 * d2 + d3 * d3);
                        if (dd < g2) {
                            ++cntL;
                            unsigned key = (dd << 16) | ((unsigned)e & 0xFFFFu);
                            #pragma unroll
                            for (int s = 0; s < TK; ++s) {   // sorted bubble-insert
                                const unsigned lo = min(key, lst[s]);
                                key = max(key, lst[s]);
                                lst[s] = lo;
                            }
                        }
                    }
                }
            }
            const unsigned cnt = __reduce_add_sync(FULLM, (unsigned)cntL);
            if (cnt >= TK || whole) break;
        }

        // merge: 10 rounds of warp-min over sorted lane heads (keys unique)
        unsigned mykey = KNONE;
        #pragma unroll
        for (int t = 0; t < TK; ++t) {
            const unsigned m = __reduce_min_sync(FULLM, lst[0]);
            if (lane == t) mykey = m;
            if (lst[0] == m) {
                #pragma unroll
                for (int s = 0; s < TK - 1; ++s) lst[s] = lst[s + 1];
                lst[TK - 1] = KNONE;
            }
        }

        // per-component precompute (lanes 0..7, width-8 trees)
        const int k = lane;
        float v = (k < KM) ? mix_logit[i * KM + k] : -INFINITY;
        float mx = v;
        #pragma unroll
        for (int d = 4; d; d >>= 1) mx = fmaxf(mx, __shfl_xor_sync(FULLM, mx, d));
        const float ex = (k < KM) ? expf(v - mx) : 0.0f;
        float sm = ex;
        #pragma unroll
        for (int d = 4; d; d >>= 1) sm += __shfl_xor_sync(FULLM, sm, d);
        const float lz = mx + logf(sm);

        float o = (k < KM) ? occ_logit[i * KM + k] : -INFINITY;
        #pragma unroll
        for (int d = 4; d; d >>= 1) o = fmaxf(o, __shfl_xor_sync(FULLM, o, d));

        if (k < KM) {
            const int bk = (i * KM + k) * 3;
            const float l0 = log_sig_off[bk], l1 = log_sig_off[bk + 1], l2 = log_sig_off[bk + 2];
            s_cmp[wid][k][0] = v - lz;
            s_cmp[wid][k][1] = mu_off[bk];
            s_cmp[wid][k][2] = mu_off[bk + 1];
            s_cmp[wid][k][3] = mu_off[bk + 2];
            s_cmp[wid][k][4] = 1.0f / (expf(2.0f * l0) + 1e-12f);
            s_cmp[wid][k][5] = 1.0f / (expf(2.0f * l1) + 1e-12f);
            s_cmp[wid][k][6] = 1.0f / (expf(2.0f * l2) + 1e-12f);
            s_cmp[wid][k][7] = 2.0f * (l0 + l1 + l2) + 3.0f * F_LOG2PI;
            s_cmp[wid][k][8] = mu_int[i * KM + k];
        }
        __syncwarp();

        // per-slot MDN + intensity (lanes 0..9)
        const bool matched = nbL > 0;
        const unsigned rm = __ballot_sync(FULLM, mykey != KNONE && lane < TK);
        const int nvalid = __popc(rm);
        float SL = 0.0f, SI = 0.0f;
        if (lane < TK) {
            const int j = (mykey != KNONE) ? (int)(mykey & 0xFFFFu)
                                           : g_fb[b * TK + (lane - nvalid)];
            const int4 lv = reinterpret_cast<const int4*>(lidx)[j];
            const float y0 = matched ? (float)(lv.w - r3) : 0.0f;
            const float y1 = matched ? (float)(lv.z - r2) : 0.0f;
            const float y2 = matched ? (float)(lv.y - r1) : 0.0f;
            const float* f = lfeat + j * CF;
            const float gi = matched ? 0.25f * (f[3] + f[7] + f[11] + f[15]) : 0.0f;

            float lp[KM]; float pm = -INFINITY;
            #pragma unroll
            for (int kk = 0; kk < KM; ++kk) {
                const float d0 = y0 - s_cmp[wid][kk][1];
                const float d1 = y1 - s_cmp[wid][kk][2];
                const float d2 = y2 - s_cmp[wid][kk][3];
                const float qv = d0 * d0 * s_cmp[wid][kk][4] + d1 * d1 * s_cmp[wid][kk][5]
                               + d2 * d2 * s_cmp[wid][kk][6];
                lp[kk] = -0.5f * (qv + s_cmp[wid][kk][7]) + s_cmp[wid][kk][0];
                pm = fmaxf(pm, lp[kk]);
            }
            float se = 0.0f;
            #pragma unroll
            for (int kk = 0; kk < KM; ++kk) se += expf(lp[kk] - pm);
            const float logp = pm + logf(se);
            SL = logp;
            float ai = 0.0f;
            #pragma unroll
            for (int kk = 0; kk < KM; ++kk)
                ai += expf(lp[kk] - logp) * fabsf(s_cmp[wid][kk][8] - gi);
            SI = ai;
        }
        #pragma unroll
        for (int d = 16; d; d >>= 1) {
            SL += __shfl_xor_sync(FULLM, SL, d);
            SI += __shfl_xor_sync(FULLM, SI, d);
        }
        if (lane == 0) {
            const float tgt = matched ? 1.0f : 0.0f;
            const float occ = tgt * softplusf(-o) + (1.0f - tgt) * softplusf(o);
            g_part[i] = make_float4(occ, tgt, tgt * SL, tgt * SI);
        }
    }

    // ---- P4: last-finishing-block deterministic reduction (ticket) ----
    __threadfence();
    __syncthreads();
    if (tid == 0) s_last = (atomicAdd(&g_done, 1) == GRD - 1);
    __syncthreads();
    if (s_last) {
        __threadfence();
        double a0 = 0, a1 = 0, a2 = 0, a3 = 0;
        for (int q = tid; q < NRR; q += 256) {
            const float4 p = g_part[q];
            a0 += p.x; a1 += p.y; a2 += p.z; a3 += p.w;
        }
        s_red[tid][0] = a0; s_red[tid][1] = a1; s_red[tid][2] = a2; s_red[tid][3] = a3;
        __syncthreads();
        for (int s = 128; s; s >>= 1) {
            if (tid < s) {
                s_red[tid][0] += s_red[tid + s][0];
                s_red[tid][1] += s_red[tid + s][1];
                s_red[tid][2] += s_red[tid + s][2];
                s_red[tid][3] += s_red[tid + s][3];
            }
            __syncthreads();
        }
        if (tid == 0) {
            const double occ_loss = s_red[0][0] / (double)NRR;
            const double cntm     = s_red[0][1];
            const double mdn_nll  = -s_red[0][2] / (cntm * (double)TK);
            const double int_loss =  s_red[0][3] / (cntm * (double)TK * (double)KM);
            out[0] = (float)(0.2 * occ_loss + 1.0 * mdn_nll + 0.1 * int_loss);
            g_done = 0;   // reset for next replay
        }
    }
}

// ---------------- launch ----------------
extern "C" void kernel_launch(void* const* d_in, const int* in_sizes, int n_in,
                              void* d_out, int out_size) {
    const float* mu_off      = (const float*)d_in[0];
    const float* log_sig_off = (const float*)d_in[1];
    const float* mu_int      = (const float*)d_in[2];
    const float* occ_logit   = (const float*)d_in[3];
    const float* mix_logit   = (const float*)d_in[4];
    const float* lfeat       = (const float*)d_in[5];
    const int*   ridx        = (const int*)d_in[6];
    const int*   lidx        = (const int*)d_in[7];
    (void)in_sizes; (void)n_in; (void)out_size;

    k_go<<<GRD, 256>>>(mu_off, log_sig_off, mu_int, occ_logit, mix_logit,
                       lfeat, ridx, lidx, (float*)d_out);
}